// round 11
// baseline (speedup 1.0000x reference)
#include <cuda_runtime.h>
#include <cuda_bf16.h>
#include <cstdint>

#define NB 4
#define NS 2048
#define NDM 1024
#define NH 16
#define NDH 64
#define NROWS (NB * NS)   // 8192

// 0.125 * log2(e) folded into Wq so softmax uses ex2 directly
#define SCALE_Q 0.18033688011112042591999058512524f

// ---------------- scratch (__device__ globals; no allocation allowed) -------
__device__ float g_o[(long)NROWS * NDM];             // out-proj result (fp32)
__device__ __nv_bfloat16 g_in_hi[3L * NROWS * NDM];  // q,k,v inputs bf16
__device__ __nv_bfloat16 g_w_hi[4L * NDM * NDM];     // Wq,Wk,Wv,Wo bf16 (Wq pre-scaled)
__device__ __nv_bfloat16 g_q_hi[(long)NROWS * NDM];  // head-major projections
__device__ __nv_bfloat16 g_k_hi[(long)NROWS * NDM];
__device__ __nv_bfloat16 g_v_hi[(long)NROWS * NDM];
__device__ __nv_bfloat16 g_ctx_hi[(long)NROWS * NDM];

// ---------------- PTX helpers (baseline compute_103-legal only) -------------
__device__ __forceinline__ uint32_t smem_u32(const void* p) {
    uint32_t a;
    asm("{ .reg .u64 t; cvta.to.shared.u64 t, %1; cvt.u32.u64 %0, t; }" : "=r"(a) : "l"(p));
    return a;
}

#define CP_ASYNC16(smem_addr, gptr) \
    asm volatile("cp.async.cg.shared.global [%0], [%1], 16;" \
                 :: "r"(smem_addr), "l"(gptr) : "memory")
#define CP_COMMIT() asm volatile("cp.async.commit_group;" ::: "memory")
#define CP_WAIT1()  asm volatile("cp.async.wait_group 1;" ::: "memory")
#define CP_WAIT0()  asm volatile("cp.async.wait_group 0;" ::: "memory")

#define LDSM_X4(r0, r1, r2, r3, addr) \
    asm volatile("ldmatrix.sync.aligned.m8n8.x4.shared.b16 {%0,%1,%2,%3}, [%4];" \
                 : "=r"(r0), "=r"(r1), "=r"(r2), "=r"(r3) : "r"(addr))
#define LDSM_X4_T(r0, r1, r2, r3, addr) \
    asm volatile("ldmatrix.sync.aligned.m8n8.x4.trans.shared.b16 {%0,%1,%2,%3}, [%4];" \
                 : "=r"(r0), "=r"(r1), "=r"(r2), "=r"(r3) : "r"(addr))

#define MMA_BF16(d, a, b0, b1) \
    asm volatile("mma.sync.aligned.m16n8k16.row.col.f32.bf16.bf16.f32 " \
                 "{%0,%1,%2,%3}, {%4,%5,%6,%7}, {%8,%9}, {%0,%1,%2,%3};" \
                 : "+f"((d)[0]), "+f"((d)[1]), "+f"((d)[2]), "+f"((d)[3]) \
                 : "r"((a)[0]), "r"((a)[1]), "r"((a)[2]), "r"((a)[3]), \
                   "r"(b0), "r"(b1))

// pack two fp32 into bf16x2: low = x0, high = x1
#define CVT_PAIR(dst, x0, x1) \
    asm("cvt.rn.bf16x2.f32 %0, %1, %2;" : "=r"(dst) : "f"(x1), "f"(x0))
// 2^x on both bf16 halves in one MUFU op
#define EX2_BF16X2(v) \
    asm("ex2.approx.ftz.bf16x2 %0, %0;" : "+r"(v))

__device__ __forceinline__ uint32_t packbf(float x0, float x1) {
    __nv_bfloat16 h0 = __float2bfloat16(x0);
    __nv_bfloat16 h1 = __float2bfloat16(x1);
    return (uint32_t)__bfloat16_as_ushort(h0) | ((uint32_t)__bfloat16_as_ushort(h1) << 16);
}

// ---------------------------------------------------------------------------
// unified cvt: fp32 -> bf16. z=0..2: q/k/v inputs (4096 blocks each);
// z=3..6: Wq/Wk/Wv/Wo (512 blocks each; Wq scaled).
// ---------------------------------------------------------------------------
__global__ __launch_bounds__(256) void cvt_kernel(const float* __restrict__ q,
                                                  const float* __restrict__ k,
                                                  const float* __restrict__ v,
                                                  const float* __restrict__ Wq,
                                                  const float* __restrict__ Wk,
                                                  const float* __restrict__ Wv,
                                                  const float* __restrict__ Wo)
{
    const int z = blockIdx.y;
    const float* srcs[7] = {q, k, v, Wq, Wk, Wv, Wo};
    if (z >= 3 && blockIdx.x >= 512) return;
    const float* src = srcs[z];
    const float scale = (z == 3) ? SCALE_Q : 1.0f;
    __nv_bfloat16* dst = (z < 3) ? (g_in_hi + (size_t)z * NROWS * NDM)
                                 : (g_w_hi + (size_t)(z - 3) * NDM * NDM);
    const size_t i = blockIdx.x * 256 + threadIdx.x;
    float4 a  = ((const float4*)src)[2 * i];
    float4 b4 = ((const float4*)src)[2 * i + 1];
    uint4 o;
    o.x = packbf(a.x * scale,  a.y * scale);
    o.y = packbf(a.z * scale,  a.w * scale);
    o.z = packbf(b4.x * scale, b4.y * scale);
    o.w = packbf(b4.z * scale, b4.w * scale);
    ((uint4*)dst)[i] = o;
}

// ---------------------------------------------------------------------------
// HMMA GEMM (1-pass bf16): C = A[M,K] @ W[N,K]^T, fp32 accum. CTA 256x128,
// BK=64, 16 warps (8M x 2N), warp tile 32x64. 3-stage cp.async pipeline,
// one sync per k-iter. 512 threads, 1 CTA/SM (smem 144KB).
// Arithmetic intensity 85 FLOP/B (vs 64 at 128x128) -> off the L2 cap.
// ---------------------------------------------------------------------------
#define STG_BYTES 49152   // per stage: A 32KB | B 16KB

__device__ __forceinline__ void gemm_load_stage(
    uint32_t smBase, int stage, int kt, int tid,
    const __nv_bfloat16* Ahi, const __nv_bfloat16* Bhi, int row0, int col0)
{
    const int kof = kt * 64;
    const uint32_t st = smBase + stage * STG_BYTES;
#pragma unroll
    for (int it = 0; it < 4; it++) {       // A: 2048 vec16
        int idx = it * 512 + tid;
        int r = idx >> 3, ch = idx & 7;
        uint32_t so = (uint32_t)(r * 128 + ((ch * 16) ^ ((r & 7) * 16)));
        CP_ASYNC16(st + so, (const char*)(Ahi + (size_t)(row0 + r) * NDM + kof) + ch * 16);
    }
#pragma unroll
    for (int it = 0; it < 2; it++) {       // B: 1024 vec16
        int idx = it * 512 + tid;
        int r = idx >> 3, ch = idx & 7;
        uint32_t so = (uint32_t)(r * 128 + ((ch * 16) ^ ((r & 7) * 16)));
        CP_ASYNC16(st + 32768 + so, (const char*)(Bhi + (size_t)(col0 + r) * NDM + kof) + ch * 16);
    }
    CP_COMMIT();
}

template <int EPI>
__global__ __launch_bounds__(512, 1) void gemm_mma_kernel()
{
    extern __shared__ char smem_raw[];
    char* smc = (char*)(((uintptr_t)smem_raw + 127) & ~(uintptr_t)127);
    const uint32_t smBase = smem_u32(smc);

    const int tid  = threadIdx.x;
    const int wid  = tid >> 5;
    const int lane = tid & 31;
    const int wm   = wid & 7;    // 8 M slabs of 32 rows
    const int wn   = wid >> 3;   // 2 N slabs of 64 cols
    const int z    = blockIdx.z;

    const __nv_bfloat16 *Ahi, *Bhi;
    if (EPI) { Ahi = g_in_hi + (size_t)z * NROWS * NDM;
               Bhi = g_w_hi + (size_t)z * NDM * NDM; }
    else     { Ahi = g_ctx_hi;
               Bhi = g_w_hi + 3ul * NDM * NDM; }

    const int row0 = blockIdx.x * 256;
    const int col0 = blockIdx.y * 128;

    float d[2][8][4];
#pragma unroll
    for (int i = 0; i < 2; i++)
#pragma unroll
        for (int j = 0; j < 8; j++)
#pragma unroll
            for (int c = 0; c < 4; c++) d[i][j][c] = 0.0f;

    const int sub = lane >> 3;
    const int l7  = lane & 7;
    const int xorS = l7 * 16;
    int rowA[2];
#pragma unroll
    for (int mi = 0; mi < 2; mi++)
        rowA[mi] = (wm * 32 + mi * 16 + (sub & 1) * 8 + l7) * 128;
    const int kselA = (sub >> 1) * 16;
    int rowB[4];
#pragma unroll
    for (int np = 0; np < 4; np++)
        rowB[np] = (wn * 64 + np * 16 + (sub >> 1) * 8 + l7) * 128;
    const int kselB = (sub & 1) * 16;

    gemm_load_stage(smBase, 0, 0, tid, Ahi, Bhi, row0, col0);
    gemm_load_stage(smBase, 1, 1, tid, Ahi, Bhi, row0, col0);

    for (int kt = 0; kt < 16; kt++) {
        if (kt + 1 < 16) CP_WAIT1();
        else             CP_WAIT0();
        __syncthreads();
        if (kt + 2 < 16)
            gemm_load_stage(smBase, (kt + 2) % 3, kt + 2, tid, Ahi, Bhi, row0, col0);

        const uint32_t sA = smBase + (kt % 3) * STG_BYTES;
        const uint32_t sB = sA + 32768;

#pragma unroll
        for (int ks = 0; ks < 4; ks++) {
            const int kb = ks * 32;
            uint32_t ah[2][4];
#pragma unroll
            for (int mi = 0; mi < 2; mi++)
                LDSM_X4(ah[mi][0], ah[mi][1], ah[mi][2], ah[mi][3],
                        sA + rowA[mi] + ((kb + kselA) ^ xorS));
#pragma unroll
            for (int np = 0; np < 4; np++) {
                uint32_t bh[4];
                LDSM_X4(bh[0], bh[1], bh[2], bh[3], sB + rowB[np] + ((kb + kselB) ^ xorS));
#pragma unroll
                for (int mi = 0; mi < 2; mi++) {
#pragma unroll
                    for (int nt = 0; nt < 2; nt++)
                        MMA_BF16(d[mi][np * 2 + nt], ah[mi], bh[nt * 2], bh[nt * 2 + 1]);
                }
            }
        }
    }

    // Epilogue
    __nv_bfloat16* Hd = (z == 0) ? g_q_hi : (z == 1) ? g_k_hi : g_v_hi;
#pragma unroll
    for (int mi = 0; mi < 2; mi++) {
        const int ra = row0 + wm * 32 + mi * 16 + (lane >> 2);
        const int rb = ra + 8;
#pragma unroll
        for (int ni = 0; ni < 8; ni++) {
            const int c = col0 + wn * 64 + ni * 8 + (lane & 3) * 2;
            if (EPI) {
                const int h = c >> 6, dh = c & 63;
                size_t i0 = (((size_t)((ra >> 11) * NH + h)) * NS + (ra & (NS - 1))) * NDH + dh;
                size_t i1 = (((size_t)((rb >> 11) * NH + h)) * NS + (rb & (NS - 1))) * NDH + dh;
                *(uint32_t*)&Hd[i0] = packbf(d[mi][ni][0], d[mi][ni][1]);
                *(uint32_t*)&Hd[i1] = packbf(d[mi][ni][2], d[mi][ni][3]);
            } else {
                *(float2*)(g_o + (size_t)ra * NDM + c) = make_float2(d[mi][ni][0], d[mi][ni][1]);
                *(float2*)(g_o + (size_t)rb * NDM + c) = make_float2(d[mi][ni][2], d[mi][ni][3]);
            }
        }
    }
}

// ---------------------------------------------------------------------------
// Flash attention on HMMA, bf16 (unchanged from R10: 164us, tensor 73%).
// CTA = 64 q rows of one (b,h), 4 warps, warp = 16 q rows x 128 keys.
// Softmax via bf16x2 ex2 (half MUFU); row sums via ones-MMA.
// smem: Q 8KB + 2 stages (K|V) 32KB = 72KB -> 3 CTAs/SM.
// ---------------------------------------------------------------------------
#define ATT_STG 32768
#define ATT_SMEM (8192 + 2 * ATT_STG)   // 73728

__device__ __forceinline__ void attn_load_kv(uint32_t smBase, int stage, int kt, int tid,
                                             const __nv_bfloat16* Kh,
                                             const __nv_bfloat16* Vh)
{
    const uint32_t st = smBase + 8192 + stage * ATT_STG;
    const int kof = kt * 128;
#pragma unroll
    for (int it = 0; it < 8; it++) {
        int idx = it * 128 + tid;          // 0..1023
        int r = idx >> 3, ch = idx & 7;
        uint32_t so = (uint32_t)(r * 128 + ((ch * 16) ^ ((r & 7) * 16)));
        CP_ASYNC16(st + so,         (const char*)(Kh + (size_t)(kof + r) * NDH) + ch * 16);
        CP_ASYNC16(st + 16384 + so, (const char*)(Vh + (size_t)(kof + r) * NDH) + ch * 16);
    }
    CP_COMMIT();
}

__global__ __launch_bounds__(128, 3) void attn_mma_kernel()
{
    extern __shared__ char smem_raw[];
    char* smc = (char*)(((uintptr_t)smem_raw + 127) & ~(uintptr_t)127);
    const uint32_t smBase = smem_u32(smc);

    const int tid  = threadIdx.x;
    const int wid  = tid >> 5;          // 0..3
    const int lane = tid & 31;
    const int sub  = lane >> 3;
    const int l7   = lane & 7;
    const int xorS = l7 * 16;

    const int bh = blockIdx.y;
    const int q0 = blockIdx.x * 64;
    const size_t hb = (size_t)bh * NS * NDH;
    const __nv_bfloat16* Qh = g_q_hi + hb;
    const __nv_bfloat16* Kh = g_k_hi + hb;
    const __nv_bfloat16* Vh = g_v_hi + hb;

    const uint32_t sQh = smBase;

#pragma unroll
    for (int it = 0; it < 4; it++) {
        int idx = it * 128 + tid;
        int r = idx >> 3, ch = idx & 7;
        uint32_t so = (uint32_t)(r * 128 + ((ch * 16) ^ ((r & 7) * 16)));
        CP_ASYNC16(sQh + so, (const char*)(Qh + (size_t)(q0 + r) * NDH) + ch * 16);
    }
    attn_load_kv(smBase, 0, 0, tid, Kh, Vh);
    attn_load_kv(smBase, 1, 1, tid, Kh, Vh);

    float ctx[8][4];
#pragma unroll
    for (int i = 0; i < 8; i++)
#pragma unroll
        for (int c = 0; c < 4; c++) ctx[i][c] = 0.0f;
    float lsD[4] = {0.0f, 0.0f, 0.0f, 0.0f};   // row-sum accumulator (MMA)
    const uint32_t ONES = 0x3F803F80u;          // bf16x2 {1.0, 1.0}

    const int rowA  = (wid * 16 + (sub & 1) * 8 + l7) * 128;
    const int kselA = (sub >> 1) * 16;
    int rowB[8];
#pragma unroll
    for (int nt = 0; nt < 8; nt++)
        rowB[nt] = (nt * 16 + (sub >> 1) * 8 + l7) * 128;
    const int kselB = (sub & 1) * 16;
    const int rowVbase = ((sub & 1) * 8 + l7) * 128;
    const int colVsel  = (sub >> 1) * 16;

    for (int kt = 0; kt < 16; kt++) {
        if (kt < 15) CP_WAIT1();
        else         CP_WAIT0();
        __syncthreads();

        const uint32_t sK  = smBase + 8192 + (kt & 1) * ATT_STG;
        const uint32_t sVh = sK + 16384;

        // ---- S = Q K^T (1-pass bf16) ----
        float S[16][4];
#pragma unroll
        for (int t = 0; t < 16; t++)
#pragma unroll
            for (int c = 0; c < 4; c++) S[t][c] = 0.0f;

#pragma unroll
        for (int ks = 0; ks < 4; ks++) {
            const int kb = ks * 32;
            uint32_t qh[4];
            LDSM_X4(qh[0], qh[1], qh[2], qh[3], sQh + rowA + ((kb + kselA) ^ xorS));
#pragma unroll
            for (int nt = 0; nt < 8; nt++) {
                uint32_t kh[4];
                LDSM_X4(kh[0], kh[1], kh[2], kh[3], sK + rowB[nt] + ((kb + kselB) ^ xorS));
                MMA_BF16(S[nt * 2],     qh, kh[0], kh[1]);
                MMA_BF16(S[nt * 2 + 1], qh, kh[2], kh[3]);
            }
        }

        // ---- P = 2^S in bf16x2 (half MUFU); row sums via ones-MMA ----
        uint32_t Pa[8][4];
#pragma unroll
        for (int kc = 0; kc < 8; kc++) {
            CVT_PAIR(Pa[kc][0], S[2 * kc][0],     S[2 * kc][1]);
            CVT_PAIR(Pa[kc][1], S[2 * kc][2],     S[2 * kc][3]);
            CVT_PAIR(Pa[kc][2], S[2 * kc + 1][0], S[2 * kc + 1][1]);
            CVT_PAIR(Pa[kc][3], S[2 * kc + 1][2], S[2 * kc + 1][3]);
            EX2_BF16X2(Pa[kc][0]);
            EX2_BF16X2(Pa[kc][1]);
            EX2_BF16X2(Pa[kc][2]);
            EX2_BF16X2(Pa[kc][3]);
            MMA_BF16(lsD, Pa[kc], ONES, ONES);
        }

        // ---- ctx += P V (1-pass bf16) ----
#pragma unroll
        for (int kc = 0; kc < 8; kc++) {
            const int rV = kc * 16 * 128 + rowVbase;
#pragma unroll
            for (int dv = 0; dv < 4; dv++) {
                const int bc = (dv * 32 + colVsel) ^ xorS;
                uint32_t vh[4];
                LDSM_X4_T(vh[0], vh[1], vh[2], vh[3], sVh + rV + bc);
                MMA_BF16(ctx[2 * dv],     Pa[kc], vh[0], vh[1]);
                MMA_BF16(ctx[2 * dv + 1], Pa[kc], vh[2], vh[3]);
            }
        }
        __syncthreads();

        if (kt + 2 < 16)
            attn_load_kv(smBase, kt & 1, kt + 2, tid, Kh, Vh);
    }

    // ---- epilogue: normalize (row sums complete in lsD), write bf16 ----
    const float inv0 = 1.0f / lsD[0];
    const float inv1 = 1.0f / lsD[2];

    const int b = bh >> 4, h = bh & 15;
    const size_t row0 = (size_t)(b * NS + q0 + wid * 16 + (lane >> 2));
    const size_t row1 = row0 + 8;
#pragma unroll
    for (int dt = 0; dt < 8; dt++) {
        const int col = h * NDH + dt * 8 + (lane & 3) * 2;
        *(uint32_t*)&g_ctx_hi[row0 * NDM + col] = packbf(ctx[dt][0] * inv0, ctx[dt][1] * inv0);
        *(uint32_t*)&g_ctx_hi[row1 * NDM + col] = packbf(ctx[dt][2] * inv1, ctx[dt][3] * inv1);
    }
}

// ---------------------------------------------------------------------------
// Residual add + LayerNorm (eps=1e-6). One 256-thread block per row.
// ---------------------------------------------------------------------------
__global__ __launch_bounds__(256) void ln_kernel(const float* __restrict__ resid,
                                                 const float* __restrict__ gamma,
                                                 const float* __restrict__ beta,
                                                 float* __restrict__ out)
{
    const int row = blockIdx.x;
    const int t = threadIdx.x;
    const float* o = g_o + (size_t)row * NDM;
    const float* r = resid + (size_t)row * NDM;

    float vals[4];
    float s = 0.0f, s2 = 0.0f;
#pragma unroll
    for (int i = 0; i < 4; i++) {
        int c = t + i * 256;
        float x = o[c] + r[c];
        vals[i] = x; s += x; s2 += x * x;
    }
#pragma unroll
    for (int off = 16; off; off >>= 1) {
        s  += __shfl_xor_sync(0xFFFFFFFFu, s, off);
        s2 += __shfl_xor_sync(0xFFFFFFFFu, s2, off);
    }
    __shared__ float ss[8], ss2[8];
    const int w = t >> 5, lane = t & 31;
    if (lane == 0) { ss[w] = s; ss2[w] = s2; }
    __syncthreads();
    if (w == 0) {
        s  = (lane < 8) ? ss[lane]  : 0.0f;
        s2 = (lane < 8) ? ss2[lane] : 0.0f;
#pragma unroll
        for (int off = 4; off; off >>= 1) {
            s  += __shfl_xor_sync(0xFFFFFFFFu, s, off);
            s2 += __shfl_xor_sync(0xFFFFFFFFu, s2, off);
        }
        if (lane == 0) { ss[0] = s; ss2[0] = s2; }
    }
    __syncthreads();
    const float mu  = ss[0] * (1.0f / NDM);
    const float var = ss2[0] * (1.0f / NDM) - mu * mu;
    const float inv = rsqrtf(var + 1e-6f);
#pragma unroll
    for (int i = 0; i < 4; i++) {
        int c = t + i * 256;
        out[(size_t)row * NDM + c] = (vals[i] - mu) * inv * gamma[c] + beta[c];
    }
}

// ---------------------------------------------------------------------------
extern "C" void kernel_launch(void* const* d_in, const int* in_sizes, int n_in,
                              void* d_out, int out_size)
{
    const float* q     = (const float*)d_in[0];
    const float* k     = (const float*)d_in[1];
    const float* v     = (const float*)d_in[2];
    const float* Wq    = (const float*)d_in[3];
    const float* Wk    = (const float*)d_in[4];
    const float* Wv    = (const float*)d_in[5];
    const float* Wo    = (const float*)d_in[6];
    const float* gamma = (const float*)d_in[7];
    const float* beta  = (const float*)d_in[8];
    float* out = (float*)d_out;

    constexpr int GSMEM = 3 * STG_BYTES + 256;   // 147712
    constexpr int ASMEM = ATT_SMEM + 256;
    cudaFuncSetAttribute(gemm_mma_kernel<1>, cudaFuncAttributeMaxDynamicSharedMemorySize, GSMEM);
    cudaFuncSetAttribute(gemm_mma_kernel<0>, cudaFuncAttributeMaxDynamicSharedMemorySize, GSMEM);
    cudaFuncSetAttribute(attn_mma_kernel, cudaFuncAttributeMaxDynamicSharedMemorySize, ASMEM);

    cvt_kernel<<<dim3(NROWS * NDM / 8 / 256, 7), 256>>>(q, k, v, Wq, Wk, Wv, Wo);

    gemm_mma_kernel<1><<<dim3(NROWS / 256, NDM / 128, 3), 512, GSMEM>>>();

    attn_mma_kernel<<<dim3(NS / 64, NB * NH), 128, ASMEM>>>();

    gemm_mma_kernel<0><<<dim3(NROWS / 256, NDM / 128, 1), 512, GSMEM>>>();

    ln_kernel<<<NROWS, 256>>>(q, gamma, beta, out);
}

// round 12
// speedup vs baseline: 1.0529x; 1.0529x over previous
#include <cuda_runtime.h>
#include <cuda_bf16.h>
#include <cstdint>

#define NB 4
#define NS 2048
#define NDM 1024
#define NH 16
#define NDH 64
#define NROWS (NB * NS)   // 8192

// 0.125 * log2(e) folded into Wq so softmax uses ex2 directly
#define SCALE_Q 0.18033688011112042591999058512524f

// ---------------- scratch (__device__ globals; no allocation allowed) -------
__device__ float g_o[(long)NROWS * NDM];             // out-proj result (fp32)
__device__ __nv_bfloat16 g_in_hi[3L * NROWS * NDM];  // q,k,v inputs bf16
__device__ __nv_bfloat16 g_w_hi[4L * NDM * NDM];     // Wq,Wk,Wv,Wo bf16 (Wq pre-scaled)
__device__ __nv_bfloat16 g_q_hi[(long)NROWS * NDM];  // head-major projections
__device__ __nv_bfloat16 g_k_hi[(long)NROWS * NDM];
__device__ __nv_bfloat16 g_v_hi[(long)NROWS * NDM];
__device__ __nv_bfloat16 g_ctx_hi[(long)NROWS * NDM];

// ---------------- PTX helpers (baseline compute_103-legal only) -------------
__device__ __forceinline__ uint32_t smem_u32(const void* p) {
    uint32_t a;
    asm("{ .reg .u64 t; cvta.to.shared.u64 t, %1; cvt.u32.u64 %0, t; }" : "=r"(a) : "l"(p));
    return a;
}

#define CP_ASYNC16(smem_addr, gptr) \
    asm volatile("cp.async.cg.shared.global [%0], [%1], 16;" \
                 :: "r"(smem_addr), "l"(gptr) : "memory")
#define CP_COMMIT() asm volatile("cp.async.commit_group;" ::: "memory")
#define CP_WAIT1()  asm volatile("cp.async.wait_group 1;" ::: "memory")
#define CP_WAIT0()  asm volatile("cp.async.wait_group 0;" ::: "memory")

#define LDSM_X4(r0, r1, r2, r3, addr) \
    asm volatile("ldmatrix.sync.aligned.m8n8.x4.shared.b16 {%0,%1,%2,%3}, [%4];" \
                 : "=r"(r0), "=r"(r1), "=r"(r2), "=r"(r3) : "r"(addr))
#define LDSM_X4_T(r0, r1, r2, r3, addr) \
    asm volatile("ldmatrix.sync.aligned.m8n8.x4.trans.shared.b16 {%0,%1,%2,%3}, [%4];" \
                 : "=r"(r0), "=r"(r1), "=r"(r2), "=r"(r3) : "r"(addr))

#define MMA_BF16(d, a, b0, b1) \
    asm volatile("mma.sync.aligned.m16n8k16.row.col.f32.bf16.bf16.f32 " \
                 "{%0,%1,%2,%3}, {%4,%5,%6,%7}, {%8,%9}, {%0,%1,%2,%3};" \
                 : "+f"((d)[0]), "+f"((d)[1]), "+f"((d)[2]), "+f"((d)[3]) \
                 : "r"((a)[0]), "r"((a)[1]), "r"((a)[2]), "r"((a)[3]), \
                   "r"(b0), "r"(b1))

// pack two fp32 into bf16x2: low = x0, high = x1
#define CVT_PAIR(dst, x0, x1) \
    asm("cvt.rn.bf16x2.f32 %0, %1, %2;" : "=r"(dst) : "f"(x1), "f"(x0))
// 2^x on both bf16 halves in one MUFU op
#define EX2_BF16X2(v) \
    asm("ex2.approx.ftz.bf16x2 %0, %0;" : "+r"(v))

__device__ __forceinline__ uint32_t packbf(float x0, float x1) {
    __nv_bfloat16 h0 = __float2bfloat16(x0);
    __nv_bfloat16 h1 = __float2bfloat16(x1);
    return (uint32_t)__bfloat16_as_ushort(h0) | ((uint32_t)__bfloat16_as_ushort(h1) << 16);
}

// ---------------------------------------------------------------------------
// unified cvt: fp32 -> bf16. z=0..2: q/k/v inputs (4096 blocks each);
// z=3..6: Wq/Wk/Wv/Wo (512 blocks each; Wq scaled).
// ---------------------------------------------------------------------------
__global__ __launch_bounds__(256) void cvt_kernel(const float* __restrict__ q,
                                                  const float* __restrict__ k,
                                                  const float* __restrict__ v,
                                                  const float* __restrict__ Wq,
                                                  const float* __restrict__ Wk,
                                                  const float* __restrict__ Wv,
                                                  const float* __restrict__ Wo)
{
    const int z = blockIdx.y;
    const float* srcs[7] = {q, k, v, Wq, Wk, Wv, Wo};
    if (z >= 3 && blockIdx.x >= 512) return;
    const float* src = srcs[z];
    const float scale = (z == 3) ? SCALE_Q : 1.0f;
    __nv_bfloat16* dst = (z < 3) ? (g_in_hi + (size_t)z * NROWS * NDM)
                                 : (g_w_hi + (size_t)(z - 3) * NDM * NDM);
    const size_t i = blockIdx.x * 256 + threadIdx.x;
    float4 a  = ((const float4*)src)[2 * i];
    float4 b4 = ((const float4*)src)[2 * i + 1];
    uint4 o;
    o.x = packbf(a.x * scale,  a.y * scale);
    o.y = packbf(a.z * scale,  a.w * scale);
    o.z = packbf(b4.x * scale, b4.y * scale);
    o.w = packbf(b4.z * scale, b4.w * scale);
    ((uint4*)dst)[i] = o;
}

// ---------------------------------------------------------------------------
// HMMA GEMM (1-pass bf16): C = A[M,K] @ W[N,K]^T, fp32 accum. CTA 128x128,
// BK=64, 8 warps (4M x 2N), warp tile 32x64. 3-stage cp.async pipeline,
// ONE sync per k-iter. __launch_bounds__(256,2): 2 CTAs/SM (smem 2x96KB).
// (R10 config — measured best; R11's 256x128/1-CTA regressed.)
// ---------------------------------------------------------------------------
#define STG_BYTES 32768   // per stage: A 16KB | B 16KB

__device__ __forceinline__ void gemm_load_stage(
    uint32_t smBase, int stage, int kt, int tid,
    const __nv_bfloat16* Ahi, const __nv_bfloat16* Bhi, int row0, int col0)
{
    const int kof = kt * 64;
    const uint32_t st = smBase + stage * STG_BYTES;
#pragma unroll
    for (int it = 0; it < 4; it++) {
        int idx = it * 256 + tid;
        int r = idx >> 3, ch = idx & 7;
        uint32_t so = (uint32_t)(r * 128 + ((ch * 16) ^ ((r & 7) * 16)));
        CP_ASYNC16(st + so,         (const char*)(Ahi + (size_t)(row0 + r) * NDM + kof) + ch * 16);
        CP_ASYNC16(st + 16384 + so, (const char*)(Bhi + (size_t)(col0 + r) * NDM + kof) + ch * 16);
    }
    CP_COMMIT();
}

template <int EPI>
__global__ __launch_bounds__(256, 2) void gemm_mma_kernel()
{
    extern __shared__ char smem_raw[];
    char* smc = (char*)(((uintptr_t)smem_raw + 127) & ~(uintptr_t)127);
    const uint32_t smBase = smem_u32(smc);

    const int tid  = threadIdx.x;
    const int wid  = tid >> 5;
    const int lane = tid & 31;
    const int wm   = wid & 3;
    const int wn   = wid >> 2;
    const int z    = blockIdx.z;

    const __nv_bfloat16 *Ahi, *Bhi;
    if (EPI) { Ahi = g_in_hi + (size_t)z * NROWS * NDM;
               Bhi = g_w_hi + (size_t)z * NDM * NDM; }
    else     { Ahi = g_ctx_hi;
               Bhi = g_w_hi + 3ul * NDM * NDM; }

    const int row0 = blockIdx.x * 128;
    const int col0 = blockIdx.y * 128;

    float d[2][8][4];
#pragma unroll
    for (int i = 0; i < 2; i++)
#pragma unroll
        for (int j = 0; j < 8; j++)
#pragma unroll
            for (int c = 0; c < 4; c++) d[i][j][c] = 0.0f;

    const int sub = lane >> 3;
    const int l7  = lane & 7;
    const int xorS = l7 * 16;
    int rowA[2];
#pragma unroll
    for (int mi = 0; mi < 2; mi++)
        rowA[mi] = (wm * 32 + mi * 16 + (sub & 1) * 8 + l7) * 128;
    const int kselA = (sub >> 1) * 16;
    int rowB[4];
#pragma unroll
    for (int np = 0; np < 4; np++)
        rowB[np] = (wn * 64 + np * 16 + (sub >> 1) * 8 + l7) * 128;
    const int kselB = (sub & 1) * 16;

    gemm_load_stage(smBase, 0, 0, tid, Ahi, Bhi, row0, col0);
    gemm_load_stage(smBase, 1, 1, tid, Ahi, Bhi, row0, col0);

    for (int kt = 0; kt < 16; kt++) {
        if (kt + 1 < 16) CP_WAIT1();
        else             CP_WAIT0();
        __syncthreads();
        if (kt + 2 < 16)
            gemm_load_stage(smBase, (kt + 2) % 3, kt + 2, tid, Ahi, Bhi, row0, col0);

        const uint32_t sA = smBase + (kt % 3) * STG_BYTES;
        const uint32_t sB = sA + 16384;

#pragma unroll
        for (int ks = 0; ks < 4; ks++) {
            const int kb = ks * 32;
            uint32_t ah[2][4];
#pragma unroll
            for (int mi = 0; mi < 2; mi++)
                LDSM_X4(ah[mi][0], ah[mi][1], ah[mi][2], ah[mi][3],
                        sA + rowA[mi] + ((kb + kselA) ^ xorS));
#pragma unroll
            for (int np = 0; np < 4; np++) {
                uint32_t bh[4];
                LDSM_X4(bh[0], bh[1], bh[2], bh[3], sB + rowB[np] + ((kb + kselB) ^ xorS));
#pragma unroll
                for (int mi = 0; mi < 2; mi++) {
#pragma unroll
                    for (int nt = 0; nt < 2; nt++)
                        MMA_BF16(d[mi][np * 2 + nt], ah[mi], bh[nt * 2], bh[nt * 2 + 1]);
                }
            }
        }
    }

    // Epilogue
    __nv_bfloat16* Hd = (z == 0) ? g_q_hi : (z == 1) ? g_k_hi : g_v_hi;
#pragma unroll
    for (int mi = 0; mi < 2; mi++) {
        const int ra = row0 + wm * 32 + mi * 16 + (lane >> 2);
        const int rb = ra + 8;
#pragma unroll
        for (int ni = 0; ni < 8; ni++) {
            const int c = col0 + wn * 64 + ni * 8 + (lane & 3) * 2;
            if (EPI) {
                const int h = c >> 6, dh = c & 63;
                size_t i0 = (((size_t)((ra >> 11) * NH + h)) * NS + (ra & (NS - 1))) * NDH + dh;
                size_t i1 = (((size_t)((rb >> 11) * NH + h)) * NS + (rb & (NS - 1))) * NDH + dh;
                *(uint32_t*)&Hd[i0] = packbf(d[mi][ni][0], d[mi][ni][1]);
                *(uint32_t*)&Hd[i1] = packbf(d[mi][ni][2], d[mi][ni][3]);
            } else {
                *(float2*)(g_o + (size_t)ra * NDM + c) = make_float2(d[mi][ni][0], d[mi][ni][1]);
                *(float2*)(g_o + (size_t)rb * NDM + c) = make_float2(d[mi][ni][2], d[mi][ni][3]);
            }
        }
    }
}

// ---------------------------------------------------------------------------
// Flash attention on HMMA, bf16 (R10: 164us, tensor 73%).
// CTA = 64 q rows of one (b,h), 4 warps, warp = 16 q rows x 128 keys.
// Softmax via bf16x2 ex2 (half MUFU); row sums via ones-MMA.
// smem: Q 8KB + 2 stages (K|V) 32KB = 72KB -> 3 CTAs/SM.
// ---------------------------------------------------------------------------
#define ATT_STG 32768
#define ATT_SMEM (8192 + 2 * ATT_STG)   // 73728

__device__ __forceinline__ void attn_load_kv(uint32_t smBase, int stage, int kt, int tid,
                                             const __nv_bfloat16* Kh,
                                             const __nv_bfloat16* Vh)
{
    const uint32_t st = smBase + 8192 + stage * ATT_STG;
    const int kof = kt * 128;
#pragma unroll
    for (int it = 0; it < 8; it++) {
        int idx = it * 128 + tid;          // 0..1023
        int r = idx >> 3, ch = idx & 7;
        uint32_t so = (uint32_t)(r * 128 + ((ch * 16) ^ ((r & 7) * 16)));
        CP_ASYNC16(st + so,         (const char*)(Kh + (size_t)(kof + r) * NDH) + ch * 16);
        CP_ASYNC16(st + 16384 + so, (const char*)(Vh + (size_t)(kof + r) * NDH) + ch * 16);
    }
    CP_COMMIT();
}

__global__ __launch_bounds__(128, 3) void attn_mma_kernel()
{
    extern __shared__ char smem_raw[];
    char* smc = (char*)(((uintptr_t)smem_raw + 127) & ~(uintptr_t)127);
    const uint32_t smBase = smem_u32(smc);

    const int tid  = threadIdx.x;
    const int wid  = tid >> 5;          // 0..3
    const int lane = tid & 31;
    const int sub  = lane >> 3;
    const int l7   = lane & 7;
    const int xorS = l7 * 16;

    const int bh = blockIdx.y;
    const int q0 = blockIdx.x * 64;
    const size_t hb = (size_t)bh * NS * NDH;
    const __nv_bfloat16* Qh = g_q_hi + hb;
    const __nv_bfloat16* Kh = g_k_hi + hb;
    const __nv_bfloat16* Vh = g_v_hi + hb;

    const uint32_t sQh = smBase;

#pragma unroll
    for (int it = 0; it < 4; it++) {
        int idx = it * 128 + tid;
        int r = idx >> 3, ch = idx & 7;
        uint32_t so = (uint32_t)(r * 128 + ((ch * 16) ^ ((r & 7) * 16)));
        CP_ASYNC16(sQh + so, (const char*)(Qh + (size_t)(q0 + r) * NDH) + ch * 16);
    }
    attn_load_kv(smBase, 0, 0, tid, Kh, Vh);
    attn_load_kv(smBase, 1, 1, tid, Kh, Vh);

    float ctx[8][4];
#pragma unroll
    for (int i = 0; i < 8; i++)
#pragma unroll
        for (int c = 0; c < 4; c++) ctx[i][c] = 0.0f;
    float lsD[4] = {0.0f, 0.0f, 0.0f, 0.0f};   // row-sum accumulator (MMA)
    const uint32_t ONES = 0x3F803F80u;          // bf16x2 {1.0, 1.0}

    const int rowA  = (wid * 16 + (sub & 1) * 8 + l7) * 128;
    const int kselA = (sub >> 1) * 16;
    int rowB[8];
#pragma unroll
    for (int nt = 0; nt < 8; nt++)
        rowB[nt] = (nt * 16 + (sub >> 1) * 8 + l7) * 128;
    const int kselB = (sub & 1) * 16;
    const int rowVbase = ((sub & 1) * 8 + l7) * 128;
    const int colVsel  = (sub >> 1) * 16;

    for (int kt = 0; kt < 16; kt++) {
        if (kt < 15) CP_WAIT1();
        else         CP_WAIT0();
        __syncthreads();

        const uint32_t sK  = smBase + 8192 + (kt & 1) * ATT_STG;
        const uint32_t sVh = sK + 16384;

        // ---- S = Q K^T (1-pass bf16) ----
        float S[16][4];
#pragma unroll
        for (int t = 0; t < 16; t++)
#pragma unroll
            for (int c = 0; c < 4; c++) S[t][c] = 0.0f;

#pragma unroll
        for (int ks = 0; ks < 4; ks++) {
            const int kb = ks * 32;
            uint32_t qh[4];
            LDSM_X4(qh[0], qh[1], qh[2], qh[3], sQh + rowA + ((kb + kselA) ^ xorS));
#pragma unroll
            for (int nt = 0; nt < 8; nt++) {
                uint32_t kh[4];
                LDSM_X4(kh[0], kh[1], kh[2], kh[3], sK + rowB[nt] + ((kb + kselB) ^ xorS));
                MMA_BF16(S[nt * 2],     qh, kh[0], kh[1]);
                MMA_BF16(S[nt * 2 + 1], qh, kh[2], kh[3]);
            }
        }

        // ---- P = 2^S in bf16x2 (half MUFU); row sums via ones-MMA ----
        uint32_t Pa[8][4];
#pragma unroll
        for (int kc = 0; kc < 8; kc++) {
            CVT_PAIR(Pa[kc][0], S[2 * kc][0],     S[2 * kc][1]);
            CVT_PAIR(Pa[kc][1], S[2 * kc][2],     S[2 * kc][3]);
            CVT_PAIR(Pa[kc][2], S[2 * kc + 1][0], S[2 * kc + 1][1]);
            CVT_PAIR(Pa[kc][3], S[2 * kc + 1][2], S[2 * kc + 1][3]);
            EX2_BF16X2(Pa[kc][0]);
            EX2_BF16X2(Pa[kc][1]);
            EX2_BF16X2(Pa[kc][2]);
            EX2_BF16X2(Pa[kc][3]);
            MMA_BF16(lsD, Pa[kc], ONES, ONES);
        }

        // ---- ctx += P V (1-pass bf16) ----
#pragma unroll
        for (int kc = 0; kc < 8; kc++) {
            const int rV = kc * 16 * 128 + rowVbase;
#pragma unroll
            for (int dv = 0; dv < 4; dv++) {
                const int bc = (dv * 32 + colVsel) ^ xorS;
                uint32_t vh[4];
                LDSM_X4_T(vh[0], vh[1], vh[2], vh[3], sVh + rV + bc);
                MMA_BF16(ctx[2 * dv],     Pa[kc], vh[0], vh[1]);
                MMA_BF16(ctx[2 * dv + 1], Pa[kc], vh[2], vh[3]);
            }
        }
        __syncthreads();

        if (kt + 2 < 16)
            attn_load_kv(smBase, kt & 1, kt + 2, tid, Kh, Vh);
    }

    // ---- epilogue: normalize (row sums complete in lsD), write bf16 ----
    const float inv0 = 1.0f / lsD[0];
    const float inv1 = 1.0f / lsD[2];

    const int b = bh >> 4, h = bh & 15;
    const size_t row0 = (size_t)(b * NS + q0 + wid * 16 + (lane >> 2));
    const size_t row1 = row0 + 8;
#pragma unroll
    for (int dt = 0; dt < 8; dt++) {
        const int col = h * NDH + dt * 8 + (lane & 3) * 2;
        *(uint32_t*)&g_ctx_hi[row0 * NDM + col] = packbf(ctx[dt][0] * inv0, ctx[dt][1] * inv0);
        *(uint32_t*)&g_ctx_hi[row1 * NDM + col] = packbf(ctx[dt][2] * inv1, ctx[dt][3] * inv1);
    }
}

// ---------------------------------------------------------------------------
// Residual add + LayerNorm (eps=1e-6). One 256-thread block per row.
// ---------------------------------------------------------------------------
__global__ __launch_bounds__(256) void ln_kernel(const float* __restrict__ resid,
                                                 const float* __restrict__ gamma,
                                                 const float* __restrict__ beta,
                                                 float* __restrict__ out)
{
    const int row = blockIdx.x;
    const int t = threadIdx.x;
    const float* o = g_o + (size_t)row * NDM;
    const float* r = resid + (size_t)row * NDM;

    float vals[4];
    float s = 0.0f, s2 = 0.0f;
#pragma unroll
    for (int i = 0; i < 4; i++) {
        int c = t + i * 256;
        float x = o[c] + r[c];
        vals[i] = x; s += x; s2 += x * x;
    }
#pragma unroll
    for (int off = 16; off; off >>= 1) {
        s  += __shfl_xor_sync(0xFFFFFFFFu, s, off);
        s2 += __shfl_xor_sync(0xFFFFFFFFu, s2, off);
    }
    __shared__ float ss[8], ss2[8];
    const int w = t >> 5, lane = t & 31;
    if (lane == 0) { ss[w] = s; ss2[w] = s2; }
    __syncthreads();
    if (w == 0) {
        s  = (lane < 8) ? ss[lane]  : 0.0f;
        s2 = (lane < 8) ? ss2[lane] : 0.0f;
#pragma unroll
        for (int off = 4; off; off >>= 1) {
            s  += __shfl_xor_sync(0xFFFFFFFFu, s, off);
            s2 += __shfl_xor_sync(0xFFFFFFFFu, s2, off);
        }
        if (lane == 0) { ss[0] = s; ss2[0] = s2; }
    }
    __syncthreads();
    const float mu  = ss[0] * (1.0f / NDM);
    const float var = ss2[0] * (1.0f / NDM) - mu * mu;
    const float inv = rsqrtf(var + 1e-6f);
#pragma unroll
    for (int i = 0; i < 4; i++) {
        int c = t + i * 256;
        out[(size_t)row * NDM + c] = (vals[i] - mu) * inv * gamma[c] + beta[c];
    }
}

// ---------------------------------------------------------------------------
extern "C" void kernel_launch(void* const* d_in, const int* in_sizes, int n_in,
                              void* d_out, int out_size)
{
    const float* q     = (const float*)d_in[0];
    const float* k     = (const float*)d_in[1];
    const float* v     = (const float*)d_in[2];
    const float* Wq    = (const float*)d_in[3];
    const float* Wk    = (const float*)d_in[4];
    const float* Wv    = (const float*)d_in[5];
    const float* Wo    = (const float*)d_in[6];
    const float* gamma = (const float*)d_in[7];
    const float* beta  = (const float*)d_in[8];
    float* out = (float*)d_out;

    constexpr int GSMEM = 3 * STG_BYTES + 256;   // 98560
    constexpr int ASMEM = ATT_SMEM + 256;
    cudaFuncSetAttribute(gemm_mma_kernel<1>, cudaFuncAttributeMaxDynamicSharedMemorySize, GSMEM);
    cudaFuncSetAttribute(gemm_mma_kernel<0>, cudaFuncAttributeMaxDynamicSharedMemorySize, GSMEM);
    cudaFuncSetAttribute(attn_mma_kernel, cudaFuncAttributeMaxDynamicSharedMemorySize, ASMEM);

    cvt_kernel<<<dim3(NROWS * NDM / 8 / 256, 7), 256>>>(q, k, v, Wq, Wk, Wv, Wo);

    gemm_mma_kernel<1><<<dim3(NROWS / 128, NDM / 128, 3), 256, GSMEM>>>();

    attn_mma_kernel<<<dim3(NS / 64, NB * NH), 128, ASMEM>>>();

    gemm_mma_kernel<0><<<dim3(NROWS / 128, NDM / 128, 1), 256, GSMEM>>>();

    ln_kernel<<<NROWS, 256>>>(q, gamma, beta, out);
}

// round 13
// speedup vs baseline: 1.1657x; 1.1072x over previous
#include <cuda_runtime.h>
#include <cuda_bf16.h>
#include <cstdint>

#define NB 4
#define NS 2048
#define NDM 1024
#define NH 16
#define NDH 64
#define NROWS (NB * NS)   // 8192

// 0.125 * log2(e) folded into Wq so softmax uses ex2 directly
#define SCALE_Q 0.18033688011112042591999058512524f

// ---------------- scratch (__device__ globals; no allocation allowed) -------
__device__ float g_o[(long)NROWS * NDM];             // out-proj result (fp32)
__device__ __nv_bfloat16 g_in_hi[3L * NROWS * NDM];  // q,k,v inputs bf16
__device__ __nv_bfloat16 g_w_hi[4L * NDM * NDM];     // Wq,Wk,Wv,Wo bf16 (Wq pre-scaled)
__device__ __nv_bfloat16 g_q_hi[(long)NROWS * NDM];  // head-major projections
__device__ __nv_bfloat16 g_k_hi[(long)NROWS * NDM];
__device__ __nv_bfloat16 g_v_hi[(long)NROWS * NDM];
__device__ __nv_bfloat16 g_ctx_hi[(long)NROWS * NDM];

// ---------------- PTX helpers (baseline compute_103-legal only) -------------
__device__ __forceinline__ uint32_t smem_u32(const void* p) {
    uint32_t a;
    asm("{ .reg .u64 t; cvta.to.shared.u64 t, %1; cvt.u32.u64 %0, t; }" : "=r"(a) : "l"(p));
    return a;
}

#define CP_ASYNC16(smem_addr, gptr) \
    asm volatile("cp.async.cg.shared.global [%0], [%1], 16;" \
                 :: "r"(smem_addr), "l"(gptr) : "memory")
#define CP_COMMIT() asm volatile("cp.async.commit_group;" ::: "memory")
#define CP_WAIT1()  asm volatile("cp.async.wait_group 1;" ::: "memory")
#define CP_WAIT0()  asm volatile("cp.async.wait_group 0;" ::: "memory")

#define LDSM_X4(r0, r1, r2, r3, addr) \
    asm volatile("ldmatrix.sync.aligned.m8n8.x4.shared.b16 {%0,%1,%2,%3}, [%4];" \
                 : "=r"(r0), "=r"(r1), "=r"(r2), "=r"(r3) : "r"(addr))
#define LDSM_X4_T(r0, r1, r2, r3, addr) \
    asm volatile("ldmatrix.sync.aligned.m8n8.x4.trans.shared.b16 {%0,%1,%2,%3}, [%4];" \
                 : "=r"(r0), "=r"(r1), "=r"(r2), "=r"(r3) : "r"(addr))

#define MMA_BF16(d, a, b0, b1) \
    asm volatile("mma.sync.aligned.m16n8k16.row.col.f32.bf16.bf16.f32 " \
                 "{%0,%1,%2,%3}, {%4,%5,%6,%7}, {%8,%9}, {%0,%1,%2,%3};" \
                 : "+f"((d)[0]), "+f"((d)[1]), "+f"((d)[2]), "+f"((d)[3]) \
                 : "r"((a)[0]), "r"((a)[1]), "r"((a)[2]), "r"((a)[3]), \
                   "r"(b0), "r"(b1))

// pack two fp32 into bf16x2: low = x0, high = x1
#define CVT_PAIR(dst, x0, x1) \
    asm("cvt.rn.bf16x2.f32 %0, %1, %2;" : "=r"(dst) : "f"(x1), "f"(x0))
// 2^x on both bf16 halves in one MUFU op
#define EX2_BF16X2(v) \
    asm("ex2.approx.ftz.bf16x2 %0, %0;" : "+r"(v))

__device__ __forceinline__ uint32_t packbf(float x0, float x1) {
    __nv_bfloat16 h0 = __float2bfloat16(x0);
    __nv_bfloat16 h1 = __float2bfloat16(x1);
    return (uint32_t)__bfloat16_as_ushort(h0) | ((uint32_t)__bfloat16_as_ushort(h1) << 16);
}

// ---------------------------------------------------------------------------
// input cvt: fp32 -> bf16, q/k/v in one launch (z selects). 8 elems/thread.
// ---------------------------------------------------------------------------
__global__ __launch_bounds__(256) void cvt_in_kernel(const float* __restrict__ q,
                                                     const float* __restrict__ k,
                                                     const float* __restrict__ v)
{
    const int z = blockIdx.y;
    const float* src = (z == 0) ? q : (z == 1) ? k : v;
    const size_t i = blockIdx.x * 256 + threadIdx.x;
    float4 a  = ((const float4*)src)[2 * i];
    float4 b4 = ((const float4*)src)[2 * i + 1];
    uint4 o;
    o.x = packbf(a.x, a.y);
    o.y = packbf(a.z, a.w);
    o.z = packbf(b4.x, b4.y);
    o.w = packbf(b4.z, b4.w);
    ((uint4*)(g_in_hi + (size_t)z * NROWS * NDM))[i] = o;
}

// weight cvt: fp32 -> bf16, all 4 weights in one launch (Wq pre-scaled)
__global__ __launch_bounds__(256) void cvt_w_kernel(const float* __restrict__ Wq,
                                                    const float* __restrict__ Wk,
                                                    const float* __restrict__ Wv,
                                                    const float* __restrict__ Wo)
{
    const int z = blockIdx.y;
    const float* src = (z == 0) ? Wq : (z == 1) ? Wk : (z == 2) ? Wv : Wo;
    const float scale = (z == 0) ? SCALE_Q : 1.0f;
    const size_t i = blockIdx.x * 256 + threadIdx.x;
    float4 a  = ((const float4*)src)[2 * i];
    float4 b4 = ((const float4*)src)[2 * i + 1];
    uint4 o;
    o.x = packbf(a.x * scale,  a.y * scale);
    o.y = packbf(a.z * scale,  a.w * scale);
    o.z = packbf(b4.x * scale, b4.y * scale);
    o.w = packbf(b4.z * scale, b4.w * scale);
    ((uint4*)(g_w_hi + (size_t)z * NDM * NDM))[i] = o;
}

// ---------------------------------------------------------------------------
// HMMA GEMM (1-pass bf16): C = A[M,K] @ W[N,K]^T, fp32 accum.
// CTA 64x128, 4 warps (2M x 2N), warp tile 32x64, BK=64.
// 3-stage cp.async pipeline, one sync per k-iter.
// __launch_bounds__(128,3): 3 CTAs/SM (smem 3x73KB), 12 warps/SM,
// three independent barrier domains — mirrors the attention kernel shape.
// ---------------------------------------------------------------------------
#define STG_BYTES 24576   // per stage: A 8KB | B 16KB

__device__ __forceinline__ void gemm_load_stage(
    uint32_t smBase, int stage, int kt, int tid,
    const __nv_bfloat16* Ahi, const __nv_bfloat16* Bhi, int row0, int col0)
{
    const int kof = kt * 64;
    const uint32_t st = smBase + stage * STG_BYTES;
#pragma unroll
    for (int it = 0; it < 4; it++) {       // A: 512 vec16
        int idx = it * 128 + tid;
        int r = idx >> 3, ch = idx & 7;
        uint32_t so = (uint32_t)(r * 128 + ((ch * 16) ^ ((r & 7) * 16)));
        CP_ASYNC16(st + so, (const char*)(Ahi + (size_t)(row0 + r) * NDM + kof) + ch * 16);
    }
#pragma unroll
    for (int it = 0; it < 8; it++) {       // B: 1024 vec16
        int idx = it * 128 + tid;
        int r = idx >> 3, ch = idx & 7;
        uint32_t so = (uint32_t)(r * 128 + ((ch * 16) ^ ((r & 7) * 16)));
        CP_ASYNC16(st + 8192 + so, (const char*)(Bhi + (size_t)(col0 + r) * NDM + kof) + ch * 16);
    }
    CP_COMMIT();
}

template <int EPI>
__global__ __launch_bounds__(128, 3) void gemm_mma_kernel()
{
    extern __shared__ char smem_raw[];
    char* smc = (char*)(((uintptr_t)smem_raw + 127) & ~(uintptr_t)127);
    const uint32_t smBase = smem_u32(smc);

    const int tid  = threadIdx.x;
    const int wid  = tid >> 5;           // 0..3
    const int lane = tid & 31;
    const int wm   = wid & 1;            // 2 M slabs of 32 rows
    const int wn   = wid >> 1;           // 2 N slabs of 64 cols
    const int z    = blockIdx.z;

    const __nv_bfloat16 *Ahi, *Bhi;
    if (EPI) { Ahi = g_in_hi + (size_t)z * NROWS * NDM;
               Bhi = g_w_hi + (size_t)z * NDM * NDM; }
    else     { Ahi = g_ctx_hi;
               Bhi = g_w_hi + 3ul * NDM * NDM; }

    const int row0 = blockIdx.x * 64;
    const int col0 = blockIdx.y * 128;

    float d[2][8][4];
#pragma unroll
    for (int i = 0; i < 2; i++)
#pragma unroll
        for (int j = 0; j < 8; j++)
#pragma unroll
            for (int c = 0; c < 4; c++) d[i][j][c] = 0.0f;

    const int sub = lane >> 3;
    const int l7  = lane & 7;
    const int xorS = l7 * 16;
    int rowA[2];
#pragma unroll
    for (int mi = 0; mi < 2; mi++)
        rowA[mi] = (wm * 32 + mi * 16 + (sub & 1) * 8 + l7) * 128;
    const int kselA = (sub >> 1) * 16;
    int rowB[4];
#pragma unroll
    for (int np = 0; np < 4; np++)
        rowB[np] = (wn * 64 + np * 16 + (sub >> 1) * 8 + l7) * 128;
    const int kselB = (sub & 1) * 16;

    gemm_load_stage(smBase, 0, 0, tid, Ahi, Bhi, row0, col0);
    gemm_load_stage(smBase, 1, 1, tid, Ahi, Bhi, row0, col0);

    for (int kt = 0; kt < 16; kt++) {
        if (kt + 1 < 16) CP_WAIT1();
        else             CP_WAIT0();
        __syncthreads();
        if (kt + 2 < 16)
            gemm_load_stage(smBase, (kt + 2) % 3, kt + 2, tid, Ahi, Bhi, row0, col0);

        const uint32_t sA = smBase + (kt % 3) * STG_BYTES;
        const uint32_t sB = sA + 8192;

#pragma unroll
        for (int ks = 0; ks < 4; ks++) {
            const int kb = ks * 32;
            uint32_t ah[2][4];
#pragma unroll
            for (int mi = 0; mi < 2; mi++)
                LDSM_X4(ah[mi][0], ah[mi][1], ah[mi][2], ah[mi][3],
                        sA + rowA[mi] + ((kb + kselA) ^ xorS));
#pragma unroll
            for (int np = 0; np < 4; np++) {
                uint32_t bh[4];
                LDSM_X4(bh[0], bh[1], bh[2], bh[3], sB + rowB[np] + ((kb + kselB) ^ xorS));
#pragma unroll
                for (int mi = 0; mi < 2; mi++) {
#pragma unroll
                    for (int nt = 0; nt < 2; nt++)
                        MMA_BF16(d[mi][np * 2 + nt], ah[mi], bh[nt * 2], bh[nt * 2 + 1]);
                }
            }
        }
    }

    // Epilogue
    __nv_bfloat16* Hd = (z == 0) ? g_q_hi : (z == 1) ? g_k_hi : g_v_hi;
#pragma unroll
    for (int mi = 0; mi < 2; mi++) {
        const int ra = row0 + wm * 32 + mi * 16 + (lane >> 2);
        const int rb = ra + 8;
#pragma unroll
        for (int ni = 0; ni < 8; ni++) {
            const int c = col0 + wn * 64 + ni * 8 + (lane & 3) * 2;
            if (EPI) {
                const int h = c >> 6, dh = c & 63;
                size_t i0 = (((size_t)((ra >> 11) * NH + h)) * NS + (ra & (NS - 1))) * NDH + dh;
                size_t i1 = (((size_t)((rb >> 11) * NH + h)) * NS + (rb & (NS - 1))) * NDH + dh;
                *(uint32_t*)&Hd[i0] = packbf(d[mi][ni][0], d[mi][ni][1]);
                *(uint32_t*)&Hd[i1] = packbf(d[mi][ni][2], d[mi][ni][3]);
            } else {
                *(float2*)(g_o + (size_t)ra * NDM + c) = make_float2(d[mi][ni][0], d[mi][ni][1]);
                *(float2*)(g_o + (size_t)rb * NDM + c) = make_float2(d[mi][ni][2], d[mi][ni][3]);
            }
        }
    }
}

// ---------------------------------------------------------------------------
// Flash attention on HMMA, bf16 (R10: 164us, tensor 73%).
// CTA = 64 q rows of one (b,h), 4 warps, warp = 16 q rows x 128 keys.
// Softmax via bf16x2 ex2 (half MUFU); row sums via ones-MMA.
// smem: Q 8KB + 2 stages (K|V) 32KB = 72KB -> 3 CTAs/SM.
// ---------------------------------------------------------------------------
#define ATT_STG 32768
#define ATT_SMEM (8192 + 2 * ATT_STG)   // 73728

__device__ __forceinline__ void attn_load_kv(uint32_t smBase, int stage, int kt, int tid,
                                             const __nv_bfloat16* Kh,
                                             const __nv_bfloat16* Vh)
{
    const uint32_t st = smBase + 8192 + stage * ATT_STG;
    const int kof = kt * 128;
#pragma unroll
    for (int it = 0; it < 8; it++) {
        int idx = it * 128 + tid;          // 0..1023
        int r = idx >> 3, ch = idx & 7;
        uint32_t so = (uint32_t)(r * 128 + ((ch * 16) ^ ((r & 7) * 16)));
        CP_ASYNC16(st + so,         (const char*)(Kh + (size_t)(kof + r) * NDH) + ch * 16);
        CP_ASYNC16(st + 16384 + so, (const char*)(Vh + (size_t)(kof + r) * NDH) + ch * 16);
    }
    CP_COMMIT();
}

__global__ __launch_bounds__(128, 3) void attn_mma_kernel()
{
    extern __shared__ char smem_raw[];
    char* smc = (char*)(((uintptr_t)smem_raw + 127) & ~(uintptr_t)127);
    const uint32_t smBase = smem_u32(smc);

    const int tid  = threadIdx.x;
    const int wid  = tid >> 5;          // 0..3
    const int lane = tid & 31;
    const int sub  = lane >> 3;
    const int l7   = lane & 7;
    const int xorS = l7 * 16;

    const int bh = blockIdx.y;
    const int q0 = blockIdx.x * 64;
    const size_t hb = (size_t)bh * NS * NDH;
    const __nv_bfloat16* Qh = g_q_hi + hb;
    const __nv_bfloat16* Kh = g_k_hi + hb;
    const __nv_bfloat16* Vh = g_v_hi + hb;

    const uint32_t sQh = smBase;

#pragma unroll
    for (int it = 0; it < 4; it++) {
        int idx = it * 128 + tid;
        int r = idx >> 3, ch = idx & 7;
        uint32_t so = (uint32_t)(r * 128 + ((ch * 16) ^ ((r & 7) * 16)));
        CP_ASYNC16(sQh + so, (const char*)(Qh + (size_t)(q0 + r) * NDH) + ch * 16);
    }
    attn_load_kv(smBase, 0, 0, tid, Kh, Vh);
    attn_load_kv(smBase, 1, 1, tid, Kh, Vh);

    float ctx[8][4];
#pragma unroll
    for (int i = 0; i < 8; i++)
#pragma unroll
        for (int c = 0; c < 4; c++) ctx[i][c] = 0.0f;
    float lsD[4] = {0.0f, 0.0f, 0.0f, 0.0f};   // row-sum accumulator (MMA)
    const uint32_t ONES = 0x3F803F80u;          // bf16x2 {1.0, 1.0}

    const int rowA  = (wid * 16 + (sub & 1) * 8 + l7) * 128;
    const int kselA = (sub >> 1) * 16;
    int rowB[8];
#pragma unroll
    for (int nt = 0; nt < 8; nt++)
        rowB[nt] = (nt * 16 + (sub >> 1) * 8 + l7) * 128;
    const int kselB = (sub & 1) * 16;
    const int rowVbase = ((sub & 1) * 8 + l7) * 128;
    const int colVsel  = (sub >> 1) * 16;

    for (int kt = 0; kt < 16; kt++) {
        if (kt < 15) CP_WAIT1();
        else         CP_WAIT0();
        __syncthreads();

        const uint32_t sK  = smBase + 8192 + (kt & 1) * ATT_STG;
        const uint32_t sVh = sK + 16384;

        // ---- S = Q K^T (1-pass bf16) ----
        float S[16][4];
#pragma unroll
        for (int t = 0; t < 16; t++)
#pragma unroll
            for (int c = 0; c < 4; c++) S[t][c] = 0.0f;

#pragma unroll
        for (int ks = 0; ks < 4; ks++) {
            const int kb = ks * 32;
            uint32_t qh[4];
            LDSM_X4(qh[0], qh[1], qh[2], qh[3], sQh + rowA + ((kb + kselA) ^ xorS));
#pragma unroll
            for (int nt = 0; nt < 8; nt++) {
                uint32_t kh[4];
                LDSM_X4(kh[0], kh[1], kh[2], kh[3], sK + rowB[nt] + ((kb + kselB) ^ xorS));
                MMA_BF16(S[nt * 2],     qh, kh[0], kh[1]);
                MMA_BF16(S[nt * 2 + 1], qh, kh[2], kh[3]);
            }
        }

        // ---- P = 2^S in bf16x2 (half MUFU); row sums via ones-MMA ----
        uint32_t Pa[8][4];
#pragma unroll
        for (int kc = 0; kc < 8; kc++) {
            CVT_PAIR(Pa[kc][0], S[2 * kc][0],     S[2 * kc][1]);
            CVT_PAIR(Pa[kc][1], S[2 * kc][2],     S[2 * kc][3]);
            CVT_PAIR(Pa[kc][2], S[2 * kc + 1][0], S[2 * kc + 1][1]);
            CVT_PAIR(Pa[kc][3], S[2 * kc + 1][2], S[2 * kc + 1][3]);
            EX2_BF16X2(Pa[kc][0]);
            EX2_BF16X2(Pa[kc][1]);
            EX2_BF16X2(Pa[kc][2]);
            EX2_BF16X2(Pa[kc][3]);
            MMA_BF16(lsD, Pa[kc], ONES, ONES);
        }

        // ---- ctx += P V (1-pass bf16) ----
#pragma unroll
        for (int kc = 0; kc < 8; kc++) {
            const int rV = kc * 16 * 128 + rowVbase;
#pragma unroll
            for (int dv = 0; dv < 4; dv++) {
                const int bc = (dv * 32 + colVsel) ^ xorS;
                uint32_t vh[4];
                LDSM_X4_T(vh[0], vh[1], vh[2], vh[3], sVh + rV + bc);
                MMA_BF16(ctx[2 * dv],     Pa[kc], vh[0], vh[1]);
                MMA_BF16(ctx[2 * dv + 1], Pa[kc], vh[2], vh[3]);
            }
        }
        __syncthreads();

        if (kt + 2 < 16)
            attn_load_kv(smBase, kt & 1, kt + 2, tid, Kh, Vh);
    }

    // ---- epilogue: normalize (row sums complete in lsD), write bf16 ----
    const float inv0 = 1.0f / lsD[0];
    const float inv1 = 1.0f / lsD[2];

    const int b = bh >> 4, h = bh & 15;
    const size_t row0 = (size_t)(b * NS + q0 + wid * 16 + (lane >> 2));
    const size_t row1 = row0 + 8;
#pragma unroll
    for (int dt = 0; dt < 8; dt++) {
        const int col = h * NDH + dt * 8 + (lane & 3) * 2;
        *(uint32_t*)&g_ctx_hi[row0 * NDM + col] = packbf(ctx[dt][0] * inv0, ctx[dt][1] * inv0);
        *(uint32_t*)&g_ctx_hi[row1 * NDM + col] = packbf(ctx[dt][2] * inv1, ctx[dt][3] * inv1);
    }
}

// ---------------------------------------------------------------------------
// Residual add + LayerNorm (eps=1e-6). One 256-thread block per row.
// ---------------------------------------------------------------------------
__global__ __launch_bounds__(256) void ln_kernel(const float* __restrict__ resid,
                                                 const float* __restrict__ gamma,
                                                 const float* __restrict__ beta,
                                                 float* __restrict__ out)
{
    const int row = blockIdx.x;
    const int t = threadIdx.x;
    const float* o = g_o + (size_t)row * NDM;
    const float* r = resid + (size_t)row * NDM;

    float vals[4];
    float s = 0.0f, s2 = 0.0f;
#pragma unroll
    for (int i = 0; i < 4; i++) {
        int c = t + i * 256;
        float x = o[c] + r[c];
        vals[i] = x; s += x; s2 += x * x;
    }
#pragma unroll
    for (int off = 16; off; off >>= 1) {
        s  += __shfl_xor_sync(0xFFFFFFFFu, s, off);
        s2 += __shfl_xor_sync(0xFFFFFFFFu, s2, off);
    }
    __shared__ float ss[8], ss2[8];
    const int w = t >> 5, lane = t & 31;
    if (lane == 0) { ss[w] = s; ss2[w] = s2; }
    __syncthreads();
    if (w == 0) {
        s  = (lane < 8) ? ss[lane]  : 0.0f;
        s2 = (lane < 8) ? ss2[lane] : 0.0f;
#pragma unroll
        for (int off = 4; off; off >>= 1) {
            s  += __shfl_xor_sync(0xFFFFFFFFu, s, off);
            s2 += __shfl_xor_sync(0xFFFFFFFFu, s2, off);
        }
        if (lane == 0) { ss[0] = s; ss2[0] = s2; }
    }
    __syncthreads();
    const float mu  = ss[0] * (1.0f / NDM);
    const float var = ss2[0] * (1.0f / NDM) - mu * mu;
    const float inv = rsqrtf(var + 1e-6f);
#pragma unroll
    for (int i = 0; i < 4; i++) {
        int c = t + i * 256;
        out[(size_t)row * NDM + c] = (vals[i] - mu) * inv * gamma[c] + beta[c];
    }
}

// ---------------------------------------------------------------------------
extern "C" void kernel_launch(void* const* d_in, const int* in_sizes, int n_in,
                              void* d_out, int out_size)
{
    const float* q     = (const float*)d_in[0];
    const float* k     = (const float*)d_in[1];
    const float* v     = (const float*)d_in[2];
    const float* Wq    = (const float*)d_in[3];
    const float* Wk    = (const float*)d_in[4];
    const float* Wv    = (const float*)d_in[5];
    const float* Wo    = (const float*)d_in[6];
    const float* gamma = (const float*)d_in[7];
    const float* beta  = (const float*)d_in[8];
    float* out = (float*)d_out;

    constexpr int GSMEM = 3 * STG_BYTES + 256;   // 73984
    constexpr int ASMEM = ATT_SMEM + 256;
    cudaFuncSetAttribute(gemm_mma_kernel<1>, cudaFuncAttributeMaxDynamicSharedMemorySize, GSMEM);
    cudaFuncSetAttribute(gemm_mma_kernel<0>, cudaFuncAttributeMaxDynamicSharedMemorySize, GSMEM);
    cudaFuncSetAttribute(attn_mma_kernel, cudaFuncAttributeMaxDynamicSharedMemorySize, ASMEM);

    cvt_in_kernel<<<dim3(NROWS * NDM / 8 / 256, 3), 256>>>(q, k, v);
    cvt_w_kernel<<<dim3(NDM * NDM / 8 / 256, 4), 256>>>(Wq, Wk, Wv, Wo);

    gemm_mma_kernel<1><<<dim3(NROWS / 64, NDM / 128, 3), 128, GSMEM>>>();

    attn_mma_kernel<<<dim3(NS / 64, NB * NH), 128, ASMEM>>>();

    gemm_mma_kernel<0><<<dim3(NROWS / 64, NDM / 128, 1), 128, GSMEM>>>();

    ln_kernel<<<NROWS, 256>>>(q, gamma, beta, out);
}

// round 14
// speedup vs baseline: 1.2097x; 1.0377x over previous
#include <cuda_runtime.h>
#include <cuda_bf16.h>
#include <cstdint>

#define NB 4
#define NS 2048
#define NDM 1024
#define NH 16
#define NDH 64
#define NROWS (NB * NS)   // 8192

#define SCALE_Q 0.18033688011112042591999058512524f

// ---------------- scratch ----------------------------------------------------
__device__ float g_o[(long)NROWS * NDM];
__device__ __nv_bfloat16 g_in_hi[3L * NROWS * NDM];
__device__ __nv_bfloat16 g_w_hi[4L * NDM * NDM];
__device__ __nv_bfloat16 g_q_hi[(long)NROWS * NDM];
__device__ __nv_bfloat16 g_k_hi[(long)NROWS * NDM];
__device__ __nv_bfloat16 g_v_hi[(long)NROWS * NDM];
__device__ __nv_bfloat16 g_ctx_hi[(long)NROWS * NDM];

// ---------------- PTX helpers -------------------------------------------------
__device__ __forceinline__ uint32_t smem_u32(const void* p) {
    uint32_t a;
    asm("{ .reg .u64 t; cvta.to.shared.u64 t, %1; cvt.u32.u64 %0, t; }" : "=r"(a) : "l"(p));
    return a;
}

#define CP_ASYNC16(smem_addr, gptr) \
    asm volatile("cp.async.cg.shared.global [%0], [%1], 16;" \
                 :: "r"(smem_addr), "l"(gptr) : "memory")
#define CP_COMMIT() asm volatile("cp.async.commit_group;" ::: "memory")
#define CP_WAIT1()  asm volatile("cp.async.wait_group 1;" ::: "memory")
#define CP_WAIT0()  asm volatile("cp.async.wait_group 0;" ::: "memory")

#define LDSM_X4(r0, r1, r2, r3, addr) \
    asm volatile("ldmatrix.sync.aligned.m8n8.x4.shared.b16 {%0,%1,%2,%3}, [%4];" \
                 : "=r"(r0), "=r"(r1), "=r"(r2), "=r"(r3) : "r"(addr))
#define LDSM_X4_T(r0, r1, r2, r3, addr) \
    asm volatile("ldmatrix.sync.aligned.m8n8.x4.trans.shared.b16 {%0,%1,%2,%3}, [%4];" \
                 : "=r"(r0), "=r"(r1), "=r"(r2), "=r"(r3) : "r"(addr))

#define MMA_BF16(d, a, b0, b1) \
    asm volatile("mma.sync.aligned.m16n8k16.row.col.f32.bf16.bf16.f32 " \
                 "{%0,%1,%2,%3}, {%4,%5,%6,%7}, {%8,%9}, {%0,%1,%2,%3};" \
                 : "+f"((d)[0]), "+f"((d)[1]), "+f"((d)[2]), "+f"((d)[3]) \
                 : "r"((a)[0]), "r"((a)[1]), "r"((a)[2]), "r"((a)[3]), \
                   "r"(b0), "r"(b1))

#define CVT_PAIR(dst, x0, x1) \
    asm("cvt.rn.bf16x2.f32 %0, %1, %2;" : "=r"(dst) : "f"(x1), "f"(x0))
#define EX2_BF16X2(v) \
    asm("ex2.approx.ftz.bf16x2 %0, %0;" : "+r"(v))

__device__ __forceinline__ uint32_t packbf(float x0, float x1) {
    __nv_bfloat16 h0 = __float2bfloat16(x0);
    __nv_bfloat16 h1 = __float2bfloat16(x1);
    return (uint32_t)__bfloat16_as_ushort(h0) | ((uint32_t)__bfloat16_as_ushort(h1) << 16);
}

// ---------------------------------------------------------------------------
// input cvt: fp32 -> bf16, q/k/v in one launch (z selects). 8 elems/thread.
// ---------------------------------------------------------------------------
__global__ __launch_bounds__(256) void cvt_in_kernel(const float* __restrict__ q,
                                                     const float* __restrict__ k,
                                                     const float* __restrict__ v)
{
    const int z = blockIdx.y;
    const float* src = (z == 0) ? q : (z == 1) ? k : v;
    const size_t i = blockIdx.x * 256 + threadIdx.x;
    float4 a  = ((const float4*)src)[2 * i];
    float4 b4 = ((const float4*)src)[2 * i + 1];
    uint4 o;
    o.x = packbf(a.x, a.y);
    o.y = packbf(a.z, a.w);
    o.z = packbf(b4.x, b4.y);
    o.w = packbf(b4.z, b4.w);
    ((uint4*)(g_in_hi + (size_t)z * NROWS * NDM))[i] = o;
}

// weight cvt: fp32 -> bf16, all 4 weights in one launch (Wq pre-scaled)
__global__ __launch_bounds__(256) void cvt_w_kernel(const float* __restrict__ Wq,
                                                    const float* __restrict__ Wk,
                                                    const float* __restrict__ Wv,
                                                    const float* __restrict__ Wo)
{
    const int z = blockIdx.y;
    const float* src = (z == 0) ? Wq : (z == 1) ? Wk : (z == 2) ? Wv : Wo;
    const float scale = (z == 0) ? SCALE_Q : 1.0f;
    const size_t i = blockIdx.x * 256 + threadIdx.x;
    float4 a  = ((const float4*)src)[2 * i];
    float4 b4 = ((const float4*)src)[2 * i + 1];
    uint4 o;
    o.x = packbf(a.x * scale,  a.y * scale);
    o.y = packbf(a.z * scale,  a.w * scale);
    o.z = packbf(b4.x * scale, b4.y * scale);
    o.w = packbf(b4.z * scale, b4.w * scale);
    ((uint4*)(g_w_hi + (size_t)z * NDM * NDM))[i] = o;
}

// ---------------------------------------------------------------------------
// HMMA GEMM (R13 config, measured best): CTA 64x128, 4 warps (2M x 2N),
// warp tile 32x64, BK=64, 3-stage cp.async, one sync/iter, 3 CTAs/SM.
// ---------------------------------------------------------------------------
#define STG_BYTES 24576   // per stage: A 8KB | B 16KB

__device__ __forceinline__ void gemm_load_stage(
    uint32_t smBase, int stage, int kt, int tid,
    const __nv_bfloat16* Ahi, const __nv_bfloat16* Bhi, int row0, int col0)
{
    const int kof = kt * 64;
    const uint32_t st = smBase + stage * STG_BYTES;
#pragma unroll
    for (int it = 0; it < 4; it++) {
        int idx = it * 128 + tid;
        int r = idx >> 3, ch = idx & 7;
        uint32_t so = (uint32_t)(r * 128 + ((ch * 16) ^ ((r & 7) * 16)));
        CP_ASYNC16(st + so, (const char*)(Ahi + (size_t)(row0 + r) * NDM + kof) + ch * 16);
    }
#pragma unroll
    for (int it = 0; it < 8; it++) {
        int idx = it * 128 + tid;
        int r = idx >> 3, ch = idx & 7;
        uint32_t so = (uint32_t)(r * 128 + ((ch * 16) ^ ((r & 7) * 16)));
        CP_ASYNC16(st + 8192 + so, (const char*)(Bhi + (size_t)(col0 + r) * NDM + kof) + ch * 16);
    }
    CP_COMMIT();
}

template <int EPI>
__global__ __launch_bounds__(128, 3) void gemm_mma_kernel()
{
    extern __shared__ char smem_raw[];
    char* smc = (char*)(((uintptr_t)smem_raw + 127) & ~(uintptr_t)127);
    const uint32_t smBase = smem_u32(smc);

    const int tid  = threadIdx.x;
    const int wid  = tid >> 5;
    const int lane = tid & 31;
    const int wm   = wid & 1;
    const int wn   = wid >> 1;
    const int z    = blockIdx.z;

    const __nv_bfloat16 *Ahi, *Bhi;
    if (EPI) { Ahi = g_in_hi + (size_t)z * NROWS * NDM;
               Bhi = g_w_hi + (size_t)z * NDM * NDM; }
    else     { Ahi = g_ctx_hi;
               Bhi = g_w_hi + 3ul * NDM * NDM; }

    const int row0 = blockIdx.x * 64;
    const int col0 = blockIdx.y * 128;

    float d[2][8][4];
#pragma unroll
    for (int i = 0; i < 2; i++)
#pragma unroll
        for (int j = 0; j < 8; j++)
#pragma unroll
            for (int c = 0; c < 4; c++) d[i][j][c] = 0.0f;

    const int sub = lane >> 3;
    const int l7  = lane & 7;
    const int xorS = l7 * 16;
    int rowA[2];
#pragma unroll
    for (int mi = 0; mi < 2; mi++)
        rowA[mi] = (wm * 32 + mi * 16 + (sub & 1) * 8 + l7) * 128;
    const int kselA = (sub >> 1) * 16;
    int rowB[4];
#pragma unroll
    for (int np = 0; np < 4; np++)
        rowB[np] = (wn * 64 + np * 16 + (sub >> 1) * 8 + l7) * 128;
    const int kselB = (sub & 1) * 16;

    gemm_load_stage(smBase, 0, 0, tid, Ahi, Bhi, row0, col0);
    gemm_load_stage(smBase, 1, 1, tid, Ahi, Bhi, row0, col0);

    for (int kt = 0; kt < 16; kt++) {
        if (kt + 1 < 16) CP_WAIT1();
        else             CP_WAIT0();
        __syncthreads();
        if (kt + 2 < 16)
            gemm_load_stage(smBase, (kt + 2) % 3, kt + 2, tid, Ahi, Bhi, row0, col0);

        const uint32_t sA = smBase + (kt % 3) * STG_BYTES;
        const uint32_t sB = sA + 8192;

#pragma unroll
        for (int ks = 0; ks < 4; ks++) {
            const int kb = ks * 32;
            uint32_t ah[2][4];
#pragma unroll
            for (int mi = 0; mi < 2; mi++)
                LDSM_X4(ah[mi][0], ah[mi][1], ah[mi][2], ah[mi][3],
                        sA + rowA[mi] + ((kb + kselA) ^ xorS));
#pragma unroll
            for (int np = 0; np < 4; np++) {
                uint32_t bh[4];
                LDSM_X4(bh[0], bh[1], bh[2], bh[3], sB + rowB[np] + ((kb + kselB) ^ xorS));
#pragma unroll
                for (int mi = 0; mi < 2; mi++) {
#pragma unroll
                    for (int nt = 0; nt < 2; nt++)
                        MMA_BF16(d[mi][np * 2 + nt], ah[mi], bh[nt * 2], bh[nt * 2 + 1]);
                }
            }
        }
    }

    // Epilogue
    __nv_bfloat16* Hd = (z == 0) ? g_q_hi : (z == 1) ? g_k_hi : g_v_hi;
#pragma unroll
    for (int mi = 0; mi < 2; mi++) {
        const int ra = row0 + wm * 32 + mi * 16 + (lane >> 2);
        const int rb = ra + 8;
#pragma unroll
        for (int ni = 0; ni < 8; ni++) {
            const int c = col0 + wn * 64 + ni * 8 + (lane & 3) * 2;
            if (EPI) {
                const int h = c >> 6, dh = c & 63;
                size_t i0 = (((size_t)((ra >> 11) * NH + h)) * NS + (ra & (NS - 1))) * NDH + dh;
                size_t i1 = (((size_t)((rb >> 11) * NH + h)) * NS + (rb & (NS - 1))) * NDH + dh;
                *(uint32_t*)&Hd[i0] = packbf(d[mi][ni][0], d[mi][ni][1]);
                *(uint32_t*)&Hd[i1] = packbf(d[mi][ni][2], d[mi][ni][3]);
            } else {
                *(float2*)(g_o + (size_t)ra * NDM + c) = make_float2(d[mi][ni][0], d[mi][ni][1]);
                *(float2*)(g_o + (size_t)rb * NDM + c) = make_float2(d[mi][ni][2], d[mi][ni][3]);
            }
        }
    }
}

// ---------------------------------------------------------------------------
// Flash attention on HMMA, bf16. CTA = 128 q rows, 4 warps, warp = 32 q rows
// x 128 keys (K/V fragments reused for 2 q-blocks: LDSM per MMA halved).
// Softmax via bf16x2 ex2; row sums via ones-MMA.
// smem: Q 16KB + 2 stages (K|V) 32KB = 80KB -> 2 CTAs/SM.
// ---------------------------------------------------------------------------
#define ATT_STG 32768
#define ATT_SMEM (16384 + 2 * ATT_STG)   // 81920

__device__ __forceinline__ void attn_load_kv(uint32_t smBase, int stage, int kt, int tid,
                                             const __nv_bfloat16* Kh,
                                             const __nv_bfloat16* Vh)
{
    const uint32_t st = smBase + 16384 + stage * ATT_STG;
    const int kof = kt * 128;
#pragma unroll
    for (int it = 0; it < 8; it++) {
        int idx = it * 128 + tid;          // 0..1023
        int r = idx >> 3, ch = idx & 7;
        uint32_t so = (uint32_t)(r * 128 + ((ch * 16) ^ ((r & 7) * 16)));
        CP_ASYNC16(st + so,         (const char*)(Kh + (size_t)(kof + r) * NDH) + ch * 16);
        CP_ASYNC16(st + 16384 + so, (const char*)(Vh + (size_t)(kof + r) * NDH) + ch * 16);
    }
    CP_COMMIT();
}

__global__ __launch_bounds__(128, 2) void attn_mma_kernel()
{
    extern __shared__ char smem_raw[];
    char* smc = (char*)(((uintptr_t)smem_raw + 127) & ~(uintptr_t)127);
    const uint32_t smBase = smem_u32(smc);

    const int tid  = threadIdx.x;
    const int wid  = tid >> 5;          // 0..3
    const int lane = tid & 31;
    const int sub  = lane >> 3;
    const int l7   = lane & 7;
    const int xorS = l7 * 16;

    const int bh = blockIdx.y;
    const int q0 = blockIdx.x * 128;
    const size_t hb = (size_t)bh * NS * NDH;
    const __nv_bfloat16* Qh = g_q_hi + hb;
    const __nv_bfloat16* Kh = g_k_hi + hb;
    const __nv_bfloat16* Vh = g_v_hi + hb;

    const uint32_t sQh = smBase;

    // Q: 128 rows x 128B = 1024 vec16
#pragma unroll
    for (int it = 0; it < 8; it++) {
        int idx = it * 128 + tid;
        int r = idx >> 3, ch = idx & 7;
        uint32_t so = (uint32_t)(r * 128 + ((ch * 16) ^ ((r & 7) * 16)));
        CP_ASYNC16(sQh + so, (const char*)(Qh + (size_t)(q0 + r) * NDH) + ch * 16);
    }
    attn_load_kv(smBase, 0, 0, tid, Kh, Vh);
    attn_load_kv(smBase, 1, 1, tid, Kh, Vh);

    float ctx[2][8][4];
#pragma unroll
    for (int mi = 0; mi < 2; mi++)
#pragma unroll
        for (int i = 0; i < 8; i++)
#pragma unroll
            for (int c = 0; c < 4; c++) ctx[mi][i][c] = 0.0f;
    float lsD[2][4];
#pragma unroll
    for (int mi = 0; mi < 2; mi++)
#pragma unroll
        for (int c = 0; c < 4; c++) lsD[mi][c] = 0.0f;
    const uint32_t ONES = 0x3F803F80u;

    // warp covers q rows [wid*32, wid*32+32): two 16-row A blocks
    int rowA[2];
#pragma unroll
    for (int mi = 0; mi < 2; mi++)
        rowA[mi] = (wid * 32 + mi * 16 + (sub & 1) * 8 + l7) * 128;
    const int kselA = (sub >> 1) * 16;
    int rowB[8];
#pragma unroll
    for (int nt = 0; nt < 8; nt++)
        rowB[nt] = (nt * 16 + (sub >> 1) * 8 + l7) * 128;
    const int kselB = (sub & 1) * 16;
    const int rowVbase = ((sub & 1) * 8 + l7) * 128;
    const int colVsel  = (sub >> 1) * 16;

    for (int kt = 0; kt < 16; kt++) {
        if (kt < 15) CP_WAIT1();
        else         CP_WAIT0();
        __syncthreads();

        const uint32_t sK  = smBase + 16384 + (kt & 1) * ATT_STG;
        const uint32_t sVh = sK + 16384;

        // ---- S = Q K^T for both 16-row blocks; K fragment reused 2x ----
        float S[2][16][4];
#pragma unroll
        for (int mi = 0; mi < 2; mi++)
#pragma unroll
            for (int t = 0; t < 16; t++)
#pragma unroll
                for (int c = 0; c < 4; c++) S[mi][t][c] = 0.0f;

#pragma unroll
        for (int ks = 0; ks < 4; ks++) {
            const int kb = ks * 32;
            uint32_t qh[2][4];
#pragma unroll
            for (int mi = 0; mi < 2; mi++)
                LDSM_X4(qh[mi][0], qh[mi][1], qh[mi][2], qh[mi][3],
                        sQh + rowA[mi] + ((kb + kselA) ^ xorS));
#pragma unroll
            for (int nt = 0; nt < 8; nt++) {
                uint32_t kh[4];
                LDSM_X4(kh[0], kh[1], kh[2], kh[3], sK + rowB[nt] + ((kb + kselB) ^ xorS));
#pragma unroll
                for (int mi = 0; mi < 2; mi++) {
                    MMA_BF16(S[mi][nt * 2],     qh[mi], kh[0], kh[1]);
                    MMA_BF16(S[mi][nt * 2 + 1], qh[mi], kh[2], kh[3]);
                }
            }
        }

        // ---- P = 2^S in bf16x2; row sums via ones-MMA ----
        uint32_t Pa[2][8][4];
#pragma unroll
        for (int mi = 0; mi < 2; mi++) {
#pragma unroll
            for (int kc = 0; kc < 8; kc++) {
                CVT_PAIR(Pa[mi][kc][0], S[mi][2 * kc][0],     S[mi][2 * kc][1]);
                CVT_PAIR(Pa[mi][kc][1], S[mi][2 * kc][2],     S[mi][2 * kc][3]);
                CVT_PAIR(Pa[mi][kc][2], S[mi][2 * kc + 1][0], S[mi][2 * kc + 1][1]);
                CVT_PAIR(Pa[mi][kc][3], S[mi][2 * kc + 1][2], S[mi][2 * kc + 1][3]);
                EX2_BF16X2(Pa[mi][kc][0]);
                EX2_BF16X2(Pa[mi][kc][1]);
                EX2_BF16X2(Pa[mi][kc][2]);
                EX2_BF16X2(Pa[mi][kc][3]);
                MMA_BF16(lsD[mi], Pa[mi][kc], ONES, ONES);
            }
        }

        // ---- ctx += P V; V fragment reused 2x ----
#pragma unroll
        for (int kc = 0; kc < 8; kc++) {
            const int rV = kc * 16 * 128 + rowVbase;
#pragma unroll
            for (int dv = 0; dv < 4; dv++) {
                const int bc = (dv * 32 + colVsel) ^ xorS;
                uint32_t vh[4];
                LDSM_X4_T(vh[0], vh[1], vh[2], vh[3], sVh + rV + bc);
#pragma unroll
                for (int mi = 0; mi < 2; mi++) {
                    MMA_BF16(ctx[mi][2 * dv],     Pa[mi][kc], vh[0], vh[1]);
                    MMA_BF16(ctx[mi][2 * dv + 1], Pa[mi][kc], vh[2], vh[3]);
                }
            }
        }
        __syncthreads();

        if (kt + 2 < 16)
            attn_load_kv(smBase, kt & 1, kt + 2, tid, Kh, Vh);
    }

    // ---- epilogue ----
    const int b = bh >> 4, h = bh & 15;
#pragma unroll
    for (int mi = 0; mi < 2; mi++) {
        const float inv0 = 1.0f / lsD[mi][0];
        const float inv1 = 1.0f / lsD[mi][2];
        const size_t row0 = (size_t)(b * NS + q0 + wid * 32 + mi * 16 + (lane >> 2));
        const size_t row1 = row0 + 8;
#pragma unroll
        for (int dt = 0; dt < 8; dt++) {
            const int col = h * NDH + dt * 8 + (lane & 3) * 2;
            *(uint32_t*)&g_ctx_hi[row0 * NDM + col] =
                packbf(ctx[mi][dt][0] * inv0, ctx[mi][dt][1] * inv0);
            *(uint32_t*)&g_ctx_hi[row1 * NDM + col] =
                packbf(ctx[mi][dt][2] * inv1, ctx[mi][dt][3] * inv1);
        }
    }
}

// ---------------------------------------------------------------------------
// Residual add + LayerNorm (eps=1e-6). One 256-thread block per row,
// float4-vectorized (4 contiguous cols per thread).
// ---------------------------------------------------------------------------
__global__ __launch_bounds__(256) void ln_kernel(const float* __restrict__ resid,
                                                 const float* __restrict__ gamma,
                                                 const float* __restrict__ beta,
                                                 float* __restrict__ out)
{
    const int row = blockIdx.x;
    const int t = threadIdx.x;
    const float4 o4 = ((const float4*)(g_o + (size_t)row * NDM))[t];
    const float4 r4 = ((const float4*)(resid + (size_t)row * NDM))[t];

    float4 x;
    x.x = o4.x + r4.x; x.y = o4.y + r4.y;
    x.z = o4.z + r4.z; x.w = o4.w + r4.w;
    float s  = (x.x + x.y) + (x.z + x.w);
    float s2 = (x.x * x.x + x.y * x.y) + (x.z * x.z + x.w * x.w);

#pragma unroll
    for (int off = 16; off; off >>= 1) {
        s  += __shfl_xor_sync(0xFFFFFFFFu, s, off);
        s2 += __shfl_xor_sync(0xFFFFFFFFu, s2, off);
    }
    __shared__ float ss[8], ss2[8];
    const int w = t >> 5, lane = t & 31;
    if (lane == 0) { ss[w] = s; ss2[w] = s2; }
    __syncthreads();
    if (w == 0) {
        s  = (lane < 8) ? ss[lane]  : 0.0f;
        s2 = (lane < 8) ? ss2[lane] : 0.0f;
#pragma unroll
        for (int off = 4; off; off >>= 1) {
            s  += __shfl_xor_sync(0xFFFFFFFFu, s, off);
            s2 += __shfl_xor_sync(0xFFFFFFFFu, s2, off);
        }
        if (lane == 0) { ss[0] = s; ss2[0] = s2; }
    }
    __syncthreads();
    const float mu  = ss[0] * (1.0f / NDM);
    const float var = ss2[0] * (1.0f / NDM) - mu * mu;
    const float inv = rsqrtf(var + 1e-6f);

    const float4 g4 = ((const float4*)gamma)[t];
    const float4 b4 = ((const float4*)beta)[t];
    float4 y;
    y.x = (x.x - mu) * inv * g4.x + b4.x;
    y.y = (x.y - mu) * inv * g4.y + b4.y;
    y.z = (x.z - mu) * inv * g4.z + b4.z;
    y.w = (x.w - mu) * inv * g4.w + b4.w;
    ((float4*)(out + (size_t)row * NDM))[t] = y;
}

// ---------------------------------------------------------------------------
extern "C" void kernel_launch(void* const* d_in, const int* in_sizes, int n_in,
                              void* d_out, int out_size)
{
    const float* q     = (const float*)d_in[0];
    const float* k     = (const float*)d_in[1];
    const float* v     = (const float*)d_in[2];
    const float* Wq    = (const float*)d_in[3];
    const float* Wk    = (const float*)d_in[4];
    const float* Wv    = (const float*)d_in[5];
    const float* Wo    = (const float*)d_in[6];
    const float* gamma = (const float*)d_in[7];
    const float* beta  = (const float*)d_in[8];
    float* out = (float*)d_out;

    constexpr int GSMEM = 3 * STG_BYTES + 256;   // 73984
    constexpr int ASMEM = ATT_SMEM + 256;        // 82176
    cudaFuncSetAttribute(gemm_mma_kernel<1>, cudaFuncAttributeMaxDynamicSharedMemorySize, GSMEM);
    cudaFuncSetAttribute(gemm_mma_kernel<0>, cudaFuncAttributeMaxDynamicSharedMemorySize, GSMEM);
    cudaFuncSetAttribute(attn_mma_kernel, cudaFuncAttributeMaxDynamicSharedMemorySize, ASMEM);

    cvt_in_kernel<<<dim3(NROWS * NDM / 8 / 256, 3), 256>>>(q, k, v);
    cvt_w_kernel<<<dim3(NDM * NDM / 8 / 256, 4), 256>>>(Wq, Wk, Wv, Wo);

    gemm_mma_kernel<1><<<dim3(NROWS / 64, NDM / 128, 3), 128, GSMEM>>>();

    attn_mma_kernel<<<dim3(NS / 128, NB * NH), 128, ASMEM>>>();

    gemm_mma_kernel<0><<<dim3(NROWS / 64, NDM / 128, 1), 128, GSMEM>>>();

    ln_kernel<<<NROWS, 256>>>(q, gamma, beta, out);
}